// round 4
// baseline (speedup 1.0000x reference)
#include <cuda_runtime.h>
#include <cuda_bf16.h>
#include <cstdint>

#define V      12288
#define E      128
#define NTI    96
#define SSTR   152              // smem row stride in bf16 (144 + 8 pad)
#define KEXT   144              // K extended with fused biases
#define SMEM_BYTES (2 * 128 * SSTR * 2)   // 77824

// ---------------------------------------------------------------------------
__device__ __nv_bfloat16 g_ctx[V * E];
__device__ __nv_bfloat16 g_tgt[V * E];

__global__ void convert_kernel(const float* __restrict__ tgt,
                               const float* __restrict__ ctx,
                               float* __restrict__ out) {
    if (blockIdx.x == 0 && threadIdx.x == 0) out[0] = 0.0f;
    int t = blockIdx.x * blockDim.x + threadIdx.x;
    int base = t * 8;
    if (base >= V * E) return;
    float4 a0 = *(const float4*)(tgt + base);
    float4 a1 = *(const float4*)(tgt + base + 4);
    float4 b0 = *(const float4*)(ctx + base);
    float4 b1 = *(const float4*)(ctx + base + 4);
    __nv_bfloat162 ta[4], ca[4];
    ta[0] = __floats2bfloat162_rn(a0.x, a0.y); ta[1] = __floats2bfloat162_rn(a0.z, a0.w);
    ta[2] = __floats2bfloat162_rn(a1.x, a1.y); ta[3] = __floats2bfloat162_rn(a1.z, a1.w);
    ca[0] = __floats2bfloat162_rn(b0.x, b0.y); ca[1] = __floats2bfloat162_rn(b0.z, b0.w);
    ca[2] = __floats2bfloat162_rn(b1.x, b1.y); ca[3] = __floats2bfloat162_rn(b1.z, b1.w);
    *(uint4*)(g_tgt + base) = *(const uint4*)ta;
    *(uint4*)(g_ctx + base) = *(const uint4*)ca;
}

// ---------------------------------------------------------------------------
__device__ __forceinline__ uint32_t smem_u32(const void* p) {
    uint32_t a;
    asm("{ .reg .u64 t; cvta.to.shared.u64 t, %1; cvt.u32.u64 %0, t; }" : "=r"(a) : "l"(p));
    return a;
}

__device__ __forceinline__ void mma_bf16(float c[4], const uint32_t a[4],
                                         const uint32_t b[2]) {
    asm volatile(
        "mma.sync.aligned.m16n8k16.row.col.f32.bf16.bf16.f32 "
        "{%0,%1,%2,%3}, {%4,%5,%6,%7}, {%8,%9}, {%0,%1,%2,%3};\n"
        : "+f"(c[0]), "+f"(c[1]), "+f"(c[2]), "+f"(c[3])
        : "r"(a[0]), "r"(a[1]), "r"(a[2]), "r"(a[3]), "r"(b[0]), "r"(b[1]));
}

__device__ __forceinline__ void ldsm_x4(uint32_t r[4], uint32_t addr) {
    asm volatile("ldmatrix.sync.aligned.m8n8.x4.shared.b16 {%0,%1,%2,%3}, [%4];"
                 : "=r"(r[0]), "=r"(r[1]), "=r"(r[2]), "=r"(r[3]) : "r"(addr));
}

// ---------------------------------------------------------------------------
// GEMM pass: warp tile 32(M) x 32(N), K=144 in 9 steps.
// A frags via LDSM.x4 (2/kstep), B frags via LDSM.x4 (2/kstep covering 4 nt).
// ---------------------------------------------------------------------------
__device__ __forceinline__ void gemm_pass(uint32_t aAddr0, uint32_t aAddr1,
                                          uint32_t bAddr0, uint32_t bAddr1,
                                          float acc[2][4][4]) {
    #pragma unroll
    for (int mt = 0; mt < 2; mt++)
        #pragma unroll
        for (int nt = 0; nt < 4; nt++)
            #pragma unroll
            for (int r = 0; r < 4; r++) acc[mt][nt][r] = 0.0f;

    #pragma unroll
    for (int ks = 0; ks < KEXT / 16; ks++) {
        const uint32_t koff = ks * 32;           // 16 bf16 = 32 bytes
        uint32_t afr[2][4], b01[4], b23[4];
        ldsm_x4(afr[0], aAddr0 + koff);
        ldsm_x4(afr[1], aAddr1 + koff);
        ldsm_x4(b01,    bAddr0 + koff);
        ldsm_x4(b23,    bAddr1 + koff);
        #pragma unroll
        for (int mt = 0; mt < 2; mt++) {
            mma_bf16(acc[mt][0], afr[mt], &b01[0]);
            mma_bf16(acc[mt][1], afr[mt], &b01[2]);
            mma_bf16(acc[mt][2], afr[mt], &b23[0]);
            mma_bf16(acc[mt][3], afr[mt], &b23[2]);
        }
    }
}

// X loads for one mt half (rows mt*16+{0,8}+g): 8 float2, streaming.
__device__ __forceinline__ void load_x8(const float* __restrict__ X,
                                        int i0, int mt, int g, int jcol,
                                        float2 xb[8]) {
    #pragma unroll
    for (int h = 0; h < 2; h++) {
        const float2* xr =
            (const float2*)(X + (size_t)(i0 + mt * 16 + h * 8 + g) * V + jcol);
        #pragma unroll
        for (int nt = 0; nt < 4; nt++) xb[h * 4 + nt] = __ldcs(xr + nt * 4);
    }
}

// Epilogue for one mt half: 16 elements/thread. acc holds dots+tb+cb already.
__device__ __forceinline__ void epi_half(const float2 xb[8], const float a[4][4],
                                         int mt, float& lsum) {
    #pragma unroll
    for (int h = 0; h < 2; h++) {
        #pragma unroll
        for (int nt = 0; nt < 4; nt++) {
            float2 xx = xb[h * 4 + nt];
            {
                float d = a[nt][h * 2 + 0] - __logf(1.0f + xx.x);
                float w = fminf(__powf(xx.x * 0.01f, 0.75f), 1.0f);
                lsum = fmaf(w * d, d, lsum);
            }
            {
                float d = a[nt][h * 2 + 1] - __logf(1.0f + xx.y);
                float w = fminf(__powf(xx.y * 0.01f, 0.75f), 1.0f);
                lsum = fmaf(w * d, d, lsum);
            }
        }
    }
}

// ---------------------------------------------------------------------------
// One 128x128 tile per block. 256 threads = 8 warps (4 M x 2 N), warp 32x64.
// ---------------------------------------------------------------------------
__global__ void __launch_bounds__(256, 2)
glove_mma(const float* __restrict__ X,
          const float* __restrict__ tb,
          const float* __restrict__ cb,
          float* __restrict__ out) {
    extern __shared__ __nv_bfloat16 smem[];
    __nv_bfloat16* As = smem;
    __nv_bfloat16* Bs = smem + 128 * SSTR;
    __shared__ float red[8];

    const int bi = blockIdx.y, bj = blockIdx.x;
    const int tid  = threadIdx.x;
    const int warp = tid >> 5;
    const int lane = tid & 31;
    const int wm   = warp >> 1;          // 0..3
    const int wn   = warp & 1;           // 0..1
    const int g    = lane >> 2;
    const int m0   = wm * 32;
    const int n0   = wn * 64;

    // ---- stage A (ctx + [1, cb]) and B (tgt + [tb, 1]) ----------------------
    {
        const __nv_bfloat16* gA = g_ctx + (size_t)(bi * 128) * E;
        const __nv_bfloat16* gB = g_tgt + (size_t)(bj * 128) * E;
        #pragma unroll
        for (int u = tid; u < 128 * 16; u += 256) {
            int row = u >> 4, part = u & 15;
            *(uint4*)(As + row * SSTR + part * 8) = *(const uint4*)(gA + row * E + part * 8);
            *(uint4*)(Bs + row * SSTR + part * 8) = *(const uint4*)(gB + row * E + part * 8);
        }
        if (tid < 128) {
            uint32_t cbb = (uint32_t)__bfloat16_as_ushort(__float2bfloat16(cb[bi * 128 + tid]));
            uint32_t tbb = (uint32_t)__bfloat16_as_ushort(__float2bfloat16(tb[bj * 128 + tid]));
            // A row: (1.0, cb, 0 x14)   B row: (tb, 1.0, 0 x14)
            uint4 za = make_uint4(0x3F80u | (cbb << 16), 0u, 0u, 0u);
            uint4 zb = make_uint4(tbb | (0x3F80u << 16), 0u, 0u, 0u);
            uint4 zz = make_uint4(0u, 0u, 0u, 0u);
            *(uint4*)(As + tid * SSTR + 128) = za;
            *(uint4*)(As + tid * SSTR + 136) = zz;
            *(uint4*)(Bs + tid * SSTR + 128) = zb;
            *(uint4*)(Bs + tid * SSTR + 136) = zz;
        }
    }
    __syncthreads();

    // ---- LDSM base addresses -------------------------------------------------
    // A x4: matrices (m0..7,k0..7),(m8..15,k0..7),(m0..7,k8..15),(m8..15,k8..15)
    //   thread t: row = t & 15, col-half = (t >> 4) * 8
    const int arow = (lane & 15);
    const int acol = (lane >> 4) << 3;
    const uint32_t aAddr0 = smem_u32(As + (m0 + arow) * SSTR + acol);
    const uint32_t aAddr1 = aAddr0 + 16 * SSTR * 2;
    // B x4 covers 2 n-strips x 2 k-halves:
    //   thread t: strip = t >> 4, k-half = (t >> 3) & 1, row = t & 7
    const int bstrip = (lane >> 4);
    const int bkh    = ((lane >> 3) & 1) << 3;
    const int brow   = (lane & 7);
    const uint32_t bAddr0 = smem_u32(Bs + (n0 + (0 + bstrip) * 8 + brow) * SSTR + bkh);
    const uint32_t bAddr1 = smem_u32(Bs + (n0 + (2 + bstrip) * 8 + brow) * SSTR + bkh);

    const int i0 = bi * 128 + m0;
    const int jw = bj * 128 + n0 + 2 * (lane & 3);

    float lsum = 0.0f;
    float acc[2][4][4];
    float2 xb0[8], xb1[8];

    // ================= pass 0 (cols n0 .. n0+31) ===============================
    load_x8(X, i0, 0, g, jw, xb0);                 // X for p0/mt0 in flight
    gemm_pass(aAddr0, aAddr1, bAddr0, bAddr1, acc);
    load_x8(X, i0, 1, g, jw, xb1);                 // X for p0/mt1 in flight
    epi_half(xb0, acc[0], 0, lsum);
    load_x8(X, i0, 0, g, jw + 32, xb0);            // X for p1/mt0 in flight
    epi_half(xb1, acc[1], 1, lsum);

    // ================= pass 1 (cols n0+32 .. n0+63) ============================
    gemm_pass(aAddr0, aAddr1, bAddr0 + 32 * SSTR * 2, bAddr1 + 32 * SSTR * 2, acc);
    load_x8(X, i0, 1, g, jw + 32, xb1);            // X for p1/mt1 in flight
    epi_half(xb0, acc[0], 0, lsum);
    epi_half(xb1, acc[1], 1, lsum);

    // ---- reduce + one atomic per block ----------------------------------------
    #pragma unroll
    for (int off = 16; off; off >>= 1) lsum += __shfl_xor_sync(0xFFFFFFFFu, lsum, off);
    if (lane == 0) red[warp] = lsum;
    __syncthreads();
    if (tid == 0) {
        float s = 0.0f;
        #pragma unroll
        for (int w = 0; w < 8; ++w) s += red[w];
        atomicAdd(out, s);
    }
}

// ---------------------------------------------------------------------------
extern "C" void kernel_launch(void* const* d_in, const int* in_sizes, int n_in,
                              void* d_out, int out_size) {
    const float* X   = (const float*)d_in[0];
    const float* te  = (const float*)d_in[1];
    const float* ce  = (const float*)d_in[2];
    const float* tbp = (const float*)d_in[3];
    const float* cbp = (const float*)d_in[4];
    float* out = (float*)d_out;

    static bool attr_set = false;
    if (!attr_set) {
        cudaFuncSetAttribute(glove_mma, cudaFuncAttributeMaxDynamicSharedMemorySize,
                             SMEM_BYTES);
        attr_set = true;
    }

    const int conv_threads = V * E / 8;
    convert_kernel<<<(conv_threads + 255) / 256, 256>>>(te, ce, out);

    dim3 grid(NTI, NTI);
    glove_mma<<<grid, 256, SMEM_BYTES>>>(X, tbp, cbp, out);
    (void)in_sizes; (void)n_in; (void)out_size;
}

// round 5
// speedup vs baseline: 1.4717x; 1.4717x over previous
#include <cuda_runtime.h>
#include <cuda_bf16.h>
#include <cstdint>

#define V      12288
#define E      128
#define NTI    96
#define SSTR   152              // smem row stride in bf16 (144 + 8 pad)
#define KEXT   144              // K extended with fused biases
#define SMEM_BYTES (2 * 128 * SSTR * 2)   // 77824

// ---------------------------------------------------------------------------
__device__ __nv_bfloat16 g_ctx[V * E];
__device__ __nv_bfloat16 g_tgt[V * E];

__global__ void convert_kernel(const float* __restrict__ tgt,
                               const float* __restrict__ ctx,
                               float* __restrict__ out) {
    if (blockIdx.x == 0 && threadIdx.x == 0) out[0] = 0.0f;
    int t = blockIdx.x * blockDim.x + threadIdx.x;
    int base = t * 8;
    if (base >= V * E) return;
    float4 a0 = *(const float4*)(tgt + base);
    float4 a1 = *(const float4*)(tgt + base + 4);
    float4 b0 = *(const float4*)(ctx + base);
    float4 b1 = *(const float4*)(ctx + base + 4);
    __nv_bfloat162 ta[4], ca[4];
    ta[0] = __floats2bfloat162_rn(a0.x, a0.y); ta[1] = __floats2bfloat162_rn(a0.z, a0.w);
    ta[2] = __floats2bfloat162_rn(a1.x, a1.y); ta[3] = __floats2bfloat162_rn(a1.z, a1.w);
    ca[0] = __floats2bfloat162_rn(b0.x, b0.y); ca[1] = __floats2bfloat162_rn(b0.z, b0.w);
    ca[2] = __floats2bfloat162_rn(b1.x, b1.y); ca[3] = __floats2bfloat162_rn(b1.z, b1.w);
    *(uint4*)(g_tgt + base) = *(const uint4*)ta;
    *(uint4*)(g_ctx + base) = *(const uint4*)ca;
}

// ---------------------------------------------------------------------------
__device__ __forceinline__ uint32_t smem_u32(const void* p) {
    uint32_t a;
    asm("{ .reg .u64 t; cvta.to.shared.u64 t, %1; cvt.u32.u64 %0, t; }" : "=r"(a) : "l"(p));
    return a;
}

__device__ __forceinline__ void mma_bf16(float c[4], const uint32_t a[4],
                                         const uint32_t b[2]) {
    asm volatile(
        "mma.sync.aligned.m16n8k16.row.col.f32.bf16.bf16.f32 "
        "{%0,%1,%2,%3}, {%4,%5,%6,%7}, {%8,%9}, {%0,%1,%2,%3};\n"
        : "+f"(c[0]), "+f"(c[1]), "+f"(c[2]), "+f"(c[3])
        : "r"(a[0]), "r"(a[1]), "r"(a[2]), "r"(a[3]), "r"(b[0]), "r"(b[1]));
}

__device__ __forceinline__ void ldsm_x4(uint32_t r[4], uint32_t addr) {
    asm volatile("ldmatrix.sync.aligned.m8n8.x4.shared.b16 {%0,%1,%2,%3}, [%4];"
                 : "=r"(r[0]), "=r"(r[1]), "=r"(r[2]), "=r"(r[3]) : "r"(addr));
}

__device__ __forceinline__ float lg2f(float v) {
    float r; asm("lg2.approx.f32 %0, %1;" : "=f"(r) : "f"(v)); return r;
}
__device__ __forceinline__ float ex2f(float v) {
    float r; asm("ex2.approx.f32 %0, %1;" : "=f"(r) : "f"(v)); return r;
}

// ---------------------------------------------------------------------------
// GEMM pass: warp tile 32(M) x 32(N), K=144 in 9 steps.
// ---------------------------------------------------------------------------
__device__ __forceinline__ void gemm_pass(uint32_t aAddr0, uint32_t aAddr1,
                                          uint32_t bAddr0, uint32_t bAddr1,
                                          float acc[2][4][4]) {
    #pragma unroll
    for (int mt = 0; mt < 2; mt++)
        #pragma unroll
        for (int nt = 0; nt < 4; nt++)
            #pragma unroll
            for (int r = 0; r < 4; r++) acc[mt][nt][r] = 0.0f;

    #pragma unroll
    for (int ks = 0; ks < KEXT / 16; ks++) {
        const uint32_t koff = ks * 32;           // 16 bf16 = 32 bytes
        uint32_t afr[2][4], b01[4], b23[4];
        ldsm_x4(afr[0], aAddr0 + koff);
        ldsm_x4(afr[1], aAddr1 + koff);
        ldsm_x4(b01,    bAddr0 + koff);
        ldsm_x4(b23,    bAddr1 + koff);
        #pragma unroll
        for (int mt = 0; mt < 2; mt++) {
            mma_bf16(acc[mt][0], afr[mt], &b01[0]);
            mma_bf16(acc[mt][1], afr[mt], &b01[2]);
            mma_bf16(acc[mt][2], afr[mt], &b23[0]);
            mma_bf16(acc[mt][3], afr[mt], &b23[2]);
        }
    }
}

// 4 float2 streaming loads from one X row.
__device__ __forceinline__ void load_x4(const float* __restrict__ X,
                                        int row, int jcol, float2 xv[4]) {
    const float2* p = (const float2*)(X + (size_t)row * V + jcol);
    #pragma unroll
    for (int q = 0; q < 4; q++) xv[q] = __ldcs(p + 4 * q);
}

// Consume one row-batch: 8 elements against acc[*][he], acc[*][he+1].
__device__ __forceinline__ void epi8(const float2 xv[4], const float a[4][4],
                                     int he, float& lsum) {
    #pragma unroll
    for (int nt = 0; nt < 4; nt++) {
        {
            float x = xv[nt].x;
            float d = fmaf(-0.69314718f, lg2f(1.0f + x), a[nt][he]);
            float w = fminf(ex2f(fmaf(0.75f, lg2f(x), -4.98289214f)), 1.0f);
            lsum = fmaf(w * d, d, lsum);
        }
        {
            float x = xv[nt].y;
            float d = fmaf(-0.69314718f, lg2f(1.0f + x), a[nt][he + 1]);
            float w = fminf(ex2f(fmaf(0.75f, lg2f(x), -4.98289214f)), 1.0f);
            lsum = fmaf(w * d, d, lsum);
        }
    }
}

// ---------------------------------------------------------------------------
// One 128x128 tile per block. 256 threads = 8 warps (4 M x 2 N), warp 32x64
// processed as two 32x32 passes.
// ---------------------------------------------------------------------------
__global__ void __launch_bounds__(256, 2)
glove_mma(const float* __restrict__ X,
          const float* __restrict__ tb,
          const float* __restrict__ cb,
          float* __restrict__ out) {
    extern __shared__ __nv_bfloat16 smem[];
    __nv_bfloat16* As = smem;
    __nv_bfloat16* Bs = smem + 128 * SSTR;
    __shared__ float red[8];

    const int bi = blockIdx.y, bj = blockIdx.x;
    const int tid  = threadIdx.x;
    const int warp = tid >> 5;
    const int lane = tid & 31;
    const int wm   = warp >> 1;          // 0..3
    const int wn   = warp & 1;           // 0..1
    const int g    = lane >> 2;
    const int m0   = wm * 32;
    const int n0   = wn * 64;

    // ---- stage A (ctx + [1, cb]) and B (tgt + [tb, 1]) ----------------------
    {
        const __nv_bfloat16* gA = g_ctx + (size_t)(bi * 128) * E;
        const __nv_bfloat16* gB = g_tgt + (size_t)(bj * 128) * E;
        #pragma unroll
        for (int u = tid; u < 128 * 16; u += 256) {
            int row = u >> 4, part = u & 15;
            *(uint4*)(As + row * SSTR + part * 8) = *(const uint4*)(gA + row * E + part * 8);
            *(uint4*)(Bs + row * SSTR + part * 8) = *(const uint4*)(gB + row * E + part * 8);
        }
        if (tid < 128) {
            uint32_t cbb = (uint32_t)__bfloat16_as_ushort(__float2bfloat16(cb[bi * 128 + tid]));
            uint32_t tbb = (uint32_t)__bfloat16_as_ushort(__float2bfloat16(tb[bj * 128 + tid]));
            uint4 za = make_uint4(0x3F80u | (cbb << 16), 0u, 0u, 0u);   // (1.0, cb)
            uint4 zb = make_uint4(tbb | (0x3F80u << 16), 0u, 0u, 0u);   // (tb, 1.0)
            uint4 zz = make_uint4(0u, 0u, 0u, 0u);
            *(uint4*)(As + tid * SSTR + 128) = za;
            *(uint4*)(As + tid * SSTR + 136) = zz;
            *(uint4*)(Bs + tid * SSTR + 128) = zb;
            *(uint4*)(Bs + tid * SSTR + 136) = zz;
        }
    }
    __syncthreads();

    // ---- LDSM base addresses -------------------------------------------------
    const int arow = (lane & 15);
    const int acol = (lane >> 4) << 3;
    const uint32_t aAddr0 = smem_u32(As + (m0 + arow) * SSTR + acol);
    const uint32_t aAddr1 = aAddr0 + 16 * SSTR * 2;
    const int bstrip = (lane >> 4);
    const int bkh    = ((lane >> 3) & 1) << 3;
    const int brow   = (lane & 7);
    const uint32_t bAddr0 = smem_u32(Bs + (n0 + (0 + bstrip) * 8 + brow) * SSTR + bkh);
    const uint32_t bAddr1 = smem_u32(Bs + (n0 + (2 + bstrip) * 8 + brow) * SSTR + bkh);

    const int i0 = bi * 128 + m0;
    const int jw = bj * 128 + n0 + 2 * (lane & 3);

    float lsum = 0.0f;
    float acc[2][4][4];
    float2 xa[4], xb2[4];

    #pragma unroll 1
    for (int pass = 0; pass < 2; pass++) {
        const int jc = jw + pass * 32;
        const uint32_t boff = (uint32_t)(pass * 32 * SSTR * 2);

        // Issue first two X row-batches, then GEMM hides their DRAM latency.
        load_x4(X, i0 + g,     jc, xa);
        load_x4(X, i0 + 8 + g, jc, xb2);

        gemm_pass(aAddr0, aAddr1, bAddr0 + boff, bAddr1 + boff, acc);

        epi8(xa,  acc[0], 0, lsum);
        load_x4(X, i0 + 16 + g, jc, xa);
        epi8(xb2, acc[0], 2, lsum);
        load_x4(X, i0 + 24 + g, jc, xb2);
        epi8(xa,  acc[1], 0, lsum);
        epi8(xb2, acc[1], 2, lsum);
    }

    // ---- reduce + one atomic per block ----------------------------------------
    #pragma unroll
    for (int off = 16; off; off >>= 1) lsum += __shfl_xor_sync(0xFFFFFFFFu, lsum, off);
    if (lane == 0) red[warp] = lsum;
    __syncthreads();
    if (tid == 0) {
        float s = 0.0f;
        #pragma unroll
        for (int w = 0; w < 8; ++w) s += red[w];
        atomicAdd(out, s);
    }
}

// ---------------------------------------------------------------------------
extern "C" void kernel_launch(void* const* d_in, const int* in_sizes, int n_in,
                              void* d_out, int out_size) {
    const float* X   = (const float*)d_in[0];
    const float* te  = (const float*)d_in[1];
    const float* ce  = (const float*)d_in[2];
    const float* tbp = (const float*)d_in[3];
    const float* cbp = (const float*)d_in[4];
    float* out = (float*)d_out;

    static bool attr_set = false;
    if (!attr_set) {
        cudaFuncSetAttribute(glove_mma, cudaFuncAttributeMaxDynamicSharedMemorySize,
                             SMEM_BYTES);
        attr_set = true;
    }

    const int conv_threads = V * E / 8;
    convert_kernel<<<(conv_threads + 255) / 256, 256>>>(te, ce, out);

    dim3 grid(NTI, NTI);
    glove_mma<<<grid, 256, SMEM_BYTES>>>(X, tbp, cbp, out);
    (void)in_sizes; (void)n_in; (void)out_size;
}